// round 9
// baseline (speedup 1.0000x reference)
#include <cuda_runtime.h>
#include <cuda_bf16.h>
#include <cstdint>

// Problem constants (Query2Context_15539191677614)
#define T_LEN 16384
#define J_LEN 64
#define D_LEN 1024
#define GRID1 296          // 2 CTAs/SM (148 SMs)
#define QTOT  (T_LEN / 4)  // 4096 row-quads

// Scratch (no cudaMalloc allowed; overwritten every replay -> deterministic)
// TRANSPOSED partials: g_partialT[k * GRID1 + b] so k_out's per-k gather is a
// contiguous, coalesced 1184B read instead of a 4KB-strided 296-line scatter.
__device__ float g_partialT[D_LEN * GRID1];
__device__ float g_bsum[GRID1];             // per-block exp sums

__device__ __forceinline__ uint32_t smem_u32(const void* p) {
    uint32_t a;
    asm("{ .reg .u64 t; cvta.to.shared.u64 t, %1; cvt.u32.u64 %0, t; }"
        : "=r"(a) : "l"(p));
    return a;
}

// ---------------------------------------------------------------------------
// Kernel 1: fused rowmax/exp + weighted-sum partials (float4 streaming).
// Same as measured-best R5 k_main except the final partial write is
// transposed (scatter, ~1.2MB into L2 — hidden under the 64MB read stream).
// ---------------------------------------------------------------------------
__global__ __launch_bounds__(1024, 2)
void k_main(const float* __restrict__ h, const float* __restrict__ s) {
    __shared__ float  e_sh[64];        // nrows <= 56
    __shared__ float4 red[4][256];     // 16KB cross-group reduce

    const int b     = blockIdx.x;
    const int q0    = (int)(((long long)b       * QTOT) / GRID1);
    const int q1    = (int)(((long long)(b + 1) * QTOT) / GRID1);
    const int nq    = q1 - q0;         // <= 14
    const int t0    = q0 * 4;
    const int nrows = nq * 4;          // <= 56
    const int tid   = threadIdx.x;
    const int w     = tid >> 5;
    const int lane  = tid & 31;

    // Phase A: warp-per-row max over J=64 (lane reads float2 -> 256B/row)
    for (int r = w; r < nrows; r += 32) {
        const float2 v = __ldcs(reinterpret_cast<const float2*>(
            s + (size_t)(t0 + r) * J_LEN + lane * 2));
        float m = fmaxf(v.x, v.y);
        #pragma unroll
        for (int off = 16; off > 0; off >>= 1)
            m = fmaxf(m, __shfl_xor_sync(0xFFFFFFFFu, m, off));
        if (lane == 0) e_sh[r] = expf(m);
    }
    __syncthreads();

    // Phase B: block exp-sum -> g_bsum[b] (warp 0)
    if (w == 0) {
        float bs = 0.0f;
        for (int r = lane; r < nrows; r += 32) bs += e_sh[r];
        #pragma unroll
        for (int off = 16; off > 0; off >>= 1)
            bs += __shfl_xor_sync(0xFFFFFFFFu, bs, off);
        if (lane == 0) g_bsum[b] = bs;
    }

    // Phase C: float4 stream over h; 4 rows per iteration
    const int g  = tid >> 8;           // row-in-quad 0..3
    const int c4 = tid & 255;          // float4 column 0..255
    float4 acc = make_float4(0.f, 0.f, 0.f, 0.f);
    const float4* __restrict__ hp = reinterpret_cast<const float4*>(
        h + (size_t)(t0 + g) * D_LEN) + c4;
    #pragma unroll 4
    for (int i = 0; i < nq; i++) {
        const float4 v = __ldcs(hp + (size_t)i * D_LEN);
        const float  e = e_sh[4 * i + g];
        acc.x = fmaf(e, v.x, acc.x);
        acc.y = fmaf(e, v.y, acc.y);
        acc.z = fmaf(e, v.z, acc.z);
        acc.w = fmaf(e, v.w, acc.w);
    }
    red[g][c4] = acc;
    __syncthreads();

    // Reduce across the 4 row-groups; thread owns column k = tid.
    // Transposed write: column-major over b.
    {
        const int kc4  = tid >> 2;
        const int comp = tid & 3;
        const float* r0p = reinterpret_cast<const float*>(&red[0][kc4]) + comp;
        const float val = r0p[0] + r0p[1024] + r0p[2048] + r0p[3072];
        g_partialT[(size_t)tid * GRID1 + b] = val;
    }
}

// ---------------------------------------------------------------------------
// Kernel 2: per-k reduce (coalesced) + normalize + TMA bulk-store broadcast.
// Block k: one coalesced read of g_partialT[k*296 .. +296) and g_bsum[296],
// warp-shuffle reduce (3 rounds, no 9-deep tree), fill 16KB smem tile with
// v = ctx_k/S, then 4 x cp.async.bulk 16KB stores covering out[k,:] (64KB).
// ---------------------------------------------------------------------------
__global__ __launch_bounds__(256)
void k_out(float* __restrict__ out) {
    __shared__ float shp[8];
    __shared__ float shs[8];
    __shared__ float v_sh;
    __shared__ __align__(128) float4 buf[1024];   // 16KB broadcast tile

    const int k    = blockIdx.x;
    const int tid  = threadIdx.x;
    const int w    = tid >> 5;
    const int lane = tid & 31;

    const float* __restrict__ P = g_partialT + (size_t)k * GRID1;

    float a  = (tid < GRID1) ? P[tid]      : 0.0f;
    float sv = (tid < GRID1) ? g_bsum[tid] : 0.0f;
    if (tid + 256 < GRID1) {              // GRID1=296: tids 0..39 pick up tail
        a  += P[tid + 256];
        sv += g_bsum[tid + 256];
    }
    #pragma unroll
    for (int off = 16; off > 0; off >>= 1) {
        a  += __shfl_xor_sync(0xFFFFFFFFu, a,  off);
        sv += __shfl_xor_sync(0xFFFFFFFFu, sv, off);
    }
    if (lane == 0) { shp[w] = a; shs[w] = sv; }
    __syncthreads();
    if (tid == 0) {
        float A = 0.0f, S = 0.0f;
        #pragma unroll
        for (int i = 0; i < 8; i++) { A += shp[i]; S += shs[i]; }
        v_sh = A / S;
    }
    __syncthreads();

    const float v = v_sh;
    const float4 vv = make_float4(v, v, v, v);
    buf[tid]       = vv;
    buf[tid + 256] = vv;
    buf[tid + 512] = vv;
    buf[tid + 768] = vv;                  // 1024 * 16B = 16KB
    __syncthreads();
    asm volatile("fence.proxy.async.shared::cta;" ::: "memory");

    if (tid == 0) {
        const uint32_t src = smem_u32(buf);
        float* row = out + (size_t)k * T_LEN;   // 64KB per output row
        #pragma unroll
        for (int c = 0; c < 4; c++) {
            asm volatile(
                "cp.async.bulk.global.shared::cta.bulk_group [%0], [%1], %2;"
                :: "l"(row + c * 4096), "r"(src), "n"(16384)
                : "memory");
        }
        asm volatile("cp.async.bulk.commit_group;" ::: "memory");
        asm volatile("cp.async.bulk.wait_group 0;" ::: "memory");
    }
}

// ---------------------------------------------------------------------------
extern "C" void kernel_launch(void* const* d_in, const int* in_sizes, int n_in,
                              void* d_out, int out_size) {
    const float* h = (const float*)d_in[0];   // [1, T, d]
    const float* s = (const float*)d_in[1];   // [T, J]
    float* out = (float*)d_out;               // [d, T]

    k_main<<<GRID1, 1024>>>(h, s);
    k_out<<<D_LEN, 256>>>(out);
}

// round 10
// speedup vs baseline: 1.1168x; 1.1168x over previous
#include <cuda_runtime.h>
#include <cuda_bf16.h>
#include <cstdint>

// Problem constants (Query2Context_15539191677614)
#define T_LEN 16384
#define J_LEN 64
#define D_LEN 1024
#define GRID1 296          // 2 CTAs/SM (148 SMs)
#define QTOT  (T_LEN / 4)  // 4096 row-quads

// Scratch (no cudaMalloc allowed).
// g_ctx is accumulated by k_main (atomicAdd) and read-then-zeroed by k_out
// (block k owns element k exclusively), so every replay starts from zeros.
__device__ float g_ctx[D_LEN];
__device__ float g_bsum[GRID1];             // per-block exp sums (overwritten)

__device__ __forceinline__ uint32_t smem_u32(const void* p) {
    uint32_t a;
    asm("{ .reg .u64 t; cvta.to.shared.u64 t, %1; cvt.u32.u64 %0, t; }"
        : "=r"(a) : "l"(p));
    return a;
}

// ---------------------------------------------------------------------------
// Kernel 1: fused rowmax/exp + weighted-sum (float4 streaming).
// Identical to measured-best R5/R7 k_main except the per-block partial is
// folded straight into g_ctx with one coalesced atomicAdd per thread
// (296 spread REDGs per address — negligible), removing the partial matrix
// and k_out's gather entirely.
// ---------------------------------------------------------------------------
__global__ __launch_bounds__(1024, 2)
void k_main(const float* __restrict__ h, const float* __restrict__ s) {
    __shared__ float  e_sh[64];        // nrows <= 56
    __shared__ float4 red[4][256];     // 16KB cross-group reduce

    const int b     = blockIdx.x;
    const int q0    = (int)(((long long)b       * QTOT) / GRID1);
    const int q1    = (int)(((long long)(b + 1) * QTOT) / GRID1);
    const int nq    = q1 - q0;         // <= 14
    const int t0    = q0 * 4;
    const int nrows = nq * 4;          // <= 56
    const int tid   = threadIdx.x;
    const int w     = tid >> 5;
    const int lane  = tid & 31;

    // Phase A: warp-per-row max over J=64 (lane reads float2 -> 256B/row)
    for (int r = w; r < nrows; r += 32) {
        const float2 v = __ldcs(reinterpret_cast<const float2*>(
            s + (size_t)(t0 + r) * J_LEN + lane * 2));
        float m = fmaxf(v.x, v.y);
        #pragma unroll
        for (int off = 16; off > 0; off >>= 1)
            m = fmaxf(m, __shfl_xor_sync(0xFFFFFFFFu, m, off));
        if (lane == 0) e_sh[r] = expf(m);
    }
    __syncthreads();

    // Phase B: block exp-sum -> g_bsum[b] (warp 0)
    if (w == 0) {
        float bs = 0.0f;
        for (int r = lane; r < nrows; r += 32) bs += e_sh[r];
        #pragma unroll
        for (int off = 16; off > 0; off >>= 1)
            bs += __shfl_xor_sync(0xFFFFFFFFu, bs, off);
        if (lane == 0) g_bsum[b] = bs;
    }

    // Phase C: float4 stream over h; 4 rows per iteration
    const int g  = tid >> 8;           // row-in-quad 0..3
    const int c4 = tid & 255;          // float4 column 0..255
    float4 acc = make_float4(0.f, 0.f, 0.f, 0.f);
    const float4* __restrict__ hp = reinterpret_cast<const float4*>(
        h + (size_t)(t0 + g) * D_LEN) + c4;
    #pragma unroll 4
    for (int i = 0; i < nq; i++) {
        const float4 v = __ldcs(hp + (size_t)i * D_LEN);
        const float  e = e_sh[4 * i + g];
        acc.x = fmaf(e, v.x, acc.x);
        acc.y = fmaf(e, v.y, acc.y);
        acc.z = fmaf(e, v.z, acc.z);
        acc.w = fmaf(e, v.w, acc.w);
    }
    red[g][c4] = acc;
    __syncthreads();

    // Reduce across the 4 row-groups; thread owns column k = tid.
    {
        const int kc4  = tid >> 2;
        const int comp = tid & 3;
        const float* r0p = reinterpret_cast<const float*>(&red[0][kc4]) + comp;
        const float val = r0p[0] + r0p[1024] + r0p[2048] + r0p[3072];
        atomicAdd(&g_ctx[tid], val);   // coalesced REDG, spread addresses
    }
}

// ---------------------------------------------------------------------------
// Kernel 2: near-zero prologue + TMA bulk-store broadcast.
// Block k: sum the 296 bsums (one contiguous 1184B coalesced read, L2-hot),
// thread 0 reads g_ctx[k] and immediately zeroes it (exclusive ownership ->
// race-free, replay-safe), v = ctx/S, fill 16KB smem tile, then 4x 16KB
// cp.async.bulk stores covering out[k, 0..T) = 64KB.
// ---------------------------------------------------------------------------
__global__ __launch_bounds__(512)
void k_out(float* __restrict__ out) {
    __shared__ float shs[16];
    __shared__ float ctx_sh;
    __shared__ float S_sh;
    __shared__ __align__(128) float4 buf[1024];   // 16KB broadcast tile

    const int k    = blockIdx.x;
    const int tid  = threadIdx.x;
    const int w    = tid >> 5;
    const int lane = tid & 31;

    // S = sum of 296 bsums (contiguous, coalesced)
    float sv = (tid < GRID1) ? g_bsum[tid] : 0.0f;
    #pragma unroll
    for (int off = 16; off > 0; off >>= 1)
        sv += __shfl_xor_sync(0xFFFFFFFFu, sv, off);
    if (lane == 0) shs[w] = sv;

    if (tid == 0) {                 // fetch + self-zero this block's ctx value
        const float c = g_ctx[k];
        g_ctx[k] = 0.0f;            // same thread: ordered; only block k touches
        ctx_sh = c;
    }
    __syncthreads();
    if (tid == 0) {
        float S = 0.0f;
        #pragma unroll
        for (int i = 0; i < 16; i++) S += shs[i];
        S_sh = S;
    }
    __syncthreads();

    const float v = ctx_sh / S_sh;
    const float4 vv = make_float4(v, v, v, v);
    buf[tid]       = vv;
    buf[tid + 512] = vv;            // 1024 * 16B = 16KB
    __syncthreads();
    asm volatile("fence.proxy.async.shared::cta;" ::: "memory");

    if (tid == 0) {
        const uint32_t src = smem_u32(buf);
        float* row = out + (size_t)k * T_LEN;   // 64KB per output row
        #pragma unroll
        for (int c = 0; c < 4; c++) {
            asm volatile(
                "cp.async.bulk.global.shared::cta.bulk_group [%0], [%1], %2;"
                :: "l"(row + c * 4096), "r"(src), "n"(16384)
                : "memory");
        }
        asm volatile("cp.async.bulk.commit_group;" ::: "memory");
        asm volatile("cp.async.bulk.wait_group 0;" ::: "memory");
    }
}

// ---------------------------------------------------------------------------
extern "C" void kernel_launch(void* const* d_in, const int* in_sizes, int n_in,
                              void* d_out, int out_size) {
    const float* h = (const float*)d_in[0];   // [1, T, d]
    const float* s = (const float*)d_in[1];   // [T, J]
    float* out = (float*)d_out;               // [d, T]

    k_main<<<GRID1, 1024>>>(h, s);
    k_out<<<D_LEN, 512>>>(out);
}

// round 13
// speedup vs baseline: 1.2530x; 1.1220x over previous
#include <cuda_runtime.h>
#include <cuda_bf16.h>
#include <cstdint>

// Problem constants (Query2Context_15539191677614)
#define T_LEN 16384
#define J_LEN 64
#define D_LEN 1024
#define GRID1 296          // 2 CTAs/SM (148 SMs)
#define QTOT  (T_LEN / 4)  // 4096 row-quads

// Scratch (no cudaMalloc allowed; overwritten every replay -> deterministic)
__device__ float g_partial[GRID1 * D_LEN];  // per-block ctx partials
__device__ float g_bsum[GRID1];             // per-block exp sums

__device__ __forceinline__ uint32_t smem_u32(const void* p) {
    uint32_t a;
    asm("{ .reg .u64 t; cvta.to.shared.u64 t, %1; cvt.u32.u64 %0, t; }"
        : "=r"(a) : "l"(p));
    return a;
}

// ---------------------------------------------------------------------------
// Kernel 1: fused rowmax/exp + weighted-sum partials.
// Same as R7 except Phase C runs TWO independent row streams (two pointers,
// two accumulators) -> 2x independent LDG.128 per iter for higher MLP.
// Stream A: quads [0, nq2), stream B: quads [nq2, 2*nq2), tail if nq odd.
// ---------------------------------------------------------------------------
__global__ __launch_bounds__(1024, 2)
void k_main(const float* __restrict__ h, const float* __restrict__ s) {
    __shared__ float  e_sh[64];        // nrows <= 56
    __shared__ float4 red[4][256];     // 16KB cross-group reduce

    const int b     = blockIdx.x;
    const int q0    = (int)(((long long)b       * QTOT) / GRID1);
    const int q1    = (int)(((long long)(b + 1) * QTOT) / GRID1);
    const int nq    = q1 - q0;         // 13 or 14
    const int t0    = q0 * 4;
    const int nrows = nq * 4;          // <= 56
    const int tid   = threadIdx.x;
    const int w     = tid >> 5;
    const int lane  = tid & 31;

    // Phase A: warp-per-row max over J=64 (lane reads float2 -> 256B/row)
    for (int r = w; r < nrows; r += 32) {
        const float2 v = __ldcs(reinterpret_cast<const float2*>(
            s + (size_t)(t0 + r) * J_LEN + lane * 2));
        float m = fmaxf(v.x, v.y);
        #pragma unroll
        for (int off = 16; off > 0; off >>= 1)
            m = fmaxf(m, __shfl_xor_sync(0xFFFFFFFFu, m, off));
        if (lane == 0) e_sh[r] = expf(m);
    }
    __syncthreads();

    // Phase B: block exp-sum -> g_bsum[b] (warp 0)
    if (w == 0) {
        float bs = 0.0f;
        for (int r = lane; r < nrows; r += 32) bs += e_sh[r];
        #pragma unroll
        for (int off = 16; off > 0; off >>= 1)
            bs += __shfl_xor_sync(0xFFFFFFFFu, bs, off);
        if (lane == 0) g_bsum[b] = bs;
    }

    // Phase C: dual-stream float4 over h; 2 independent quads per iteration.
    // One quad = 4 rows = 4*D_LEN floats = D_LEN float4s.
    const int g  = tid >> 8;           // row-in-quad 0..3
    const int c4 = tid & 255;          // float4 column 0..255
    const int nq2 = nq >> 1;
    float4 acc0 = make_float4(0.f, 0.f, 0.f, 0.f);
    float4 acc1 = make_float4(0.f, 0.f, 0.f, 0.f);
    const float4* __restrict__ hpA = reinterpret_cast<const float4*>(
        h + (size_t)(t0 + g) * D_LEN) + c4;
    const float4* __restrict__ hpB = hpA + (size_t)nq2 * D_LEN;
    #pragma unroll 4
    for (int i = 0; i < nq2; i++) {
        const float4 v0 = __ldcs(hpA + (size_t)i * D_LEN);
        const float4 v1 = __ldcs(hpB + (size_t)i * D_LEN);
        const float  e0 = e_sh[4 * i + g];
        const float  e1 = e_sh[4 * (nq2 + i) + g];
        acc0.x = fmaf(e0, v0.x, acc0.x);  acc1.x = fmaf(e1, v1.x, acc1.x);
        acc0.y = fmaf(e0, v0.y, acc0.y);  acc1.y = fmaf(e1, v1.y, acc1.y);
        acc0.z = fmaf(e0, v0.z, acc0.z);  acc1.z = fmaf(e1, v1.z, acc1.z);
        acc0.w = fmaf(e0, v0.w, acc0.w);  acc1.w = fmaf(e1, v1.w, acc1.w);
    }
    if (nq & 1) {                       // odd nq: last quad
        const int i = nq - 1;
        const float4 v = __ldcs(hpA + (size_t)i * D_LEN);
        const float  e = e_sh[4 * i + g];
        acc0.x = fmaf(e, v.x, acc0.x);
        acc0.y = fmaf(e, v.y, acc0.y);
        acc0.z = fmaf(e, v.z, acc0.z);
        acc0.w = fmaf(e, v.w, acc0.w);
    }
    red[g][c4] = make_float4(acc0.x + acc1.x, acc0.y + acc1.y,
                             acc0.z + acc1.z, acc0.w + acc1.w);
    __syncthreads();

    // Reduce across the 4 row-groups; thread owns column k = tid
    {
        const int kc4  = tid >> 2;
        const int comp = tid & 3;
        const float* r0p = reinterpret_cast<const float*>(&red[0][kc4]) + comp;
        g_partial[b * D_LEN + tid] = r0p[0] + r0p[1024] + r0p[2048] + r0p[3072];
    }
}

// ---------------------------------------------------------------------------
// Kernel 2: R7-VERBATIM (known correct, 14.4us).
// Block k: gather 296 partials & bsums (L2-hot), tree-reduce, compute
// v = ctx_k / S, fill a 16KB smem tile with v, then issue 4 async
// cp.async.bulk stores (16KB each) covering out[k, 0..T) = 64KB.
// Fence executed by ALL threads before the elected thread issues stores.
// ---------------------------------------------------------------------------
__global__ __launch_bounds__(512)
void k_out(float* __restrict__ out) {
    __shared__ float  shp[512];
    __shared__ float  shs[512];
    __shared__ __align__(128) float4 buf[1024];   // 16KB broadcast tile

    const int k   = blockIdx.x;
    const int tid = threadIdx.x;

    shp[tid] = (tid < GRID1) ? g_partial[tid * D_LEN + k] : 0.0f;
    shs[tid] = (tid < GRID1) ? g_bsum[tid]                : 0.0f;
    __syncthreads();

    #pragma unroll
    for (int off = 256; off > 0; off >>= 1) {
        if (tid < off) {
            shp[tid] += shp[tid + off];
            shs[tid] += shs[tid + off];
        }
        __syncthreads();
    }

    const float v = shp[0] / shs[0];
    const float4 vv = make_float4(v, v, v, v);
    buf[tid]       = vv;                 // 512 * 16B
    buf[tid + 512] = vv;                 // + 512 * 16B = 16KB
    __syncthreads();
    asm volatile("fence.proxy.async.shared::cta;" ::: "memory");

    if (tid == 0) {
        const uint32_t src = smem_u32(buf);
        float* row = out + (size_t)k * T_LEN;   // 64KB per row
        #pragma unroll
        for (int c = 0; c < 4; c++) {
            asm volatile(
                "cp.async.bulk.global.shared::cta.bulk_group [%0], [%1], %2;"
                :: "l"(row + c * 4096), "r"(src), "n"(16384)
                : "memory");
        }
        asm volatile("cp.async.bulk.commit_group;" ::: "memory");
        asm volatile("cp.async.bulk.wait_group 0;" ::: "memory");
    }
}

// ---------------------------------------------------------------------------
extern "C" void kernel_launch(void* const* d_in, const int* in_sizes, int n_in,
                              void* d_out, int out_size) {
    const float* h = (const float*)d_in[0];   // [1, T, d]
    const float* s = (const float*)d_in[1];   // [T, J]
    float* out = (float*)d_out;               // [d, T]

    k_main<<<GRID1, 1024>>>(h, s);
    k_out<<<D_LEN, 512>>>(out);
}